// round 16
// baseline (speedup 1.0000x reference)
#include <cuda_runtime.h>
#include <cstdint>

// GHM loss — single fused kernel, one pass over x/target (268 MB).
// R15: DECOUPLED MEMORY PATH. cp.async.bulk (UBLKCP) stages 4KB x/t tiles
// into a 2-stage smem pipeline (mbarrier expect_tx); the per-SM copy engine
// keeps transfers in flight independent of warp scheduling (attacks the 36%
// DRAM idle). Consumers read via LDS.128. Hot-loop math unchanged from the
// best kernel (R11): RZ-FMA bin, transposed smem hist, K-offset
// count-in-value (v = count*16384 + loss2_sum, count<=28<32, exact recovery
// via rintf(v/K)). Persistent single-wave grid: 1184 blocks, 27 tiles each
// + guarded tail tile for blocks < 800 (27*1184 + 800 = 32768 = all tiles).
// Last block (threadfence + counter) finalizes beta, writes mean, resets state.

#define BINS   10
#define TPB    256
#define BLOCKS (148 * 8)              // 1184 = one full wave at 8 blocks/SM
#define NTILES 32768                  // 2^23 float4s / 256 per tile
#define FULLT  27                     // tiles done by every block
#define XBLK   800                    // blocks doing one extra tile
#define TILE_BYTES (TPB * 16)         // 4096 bytes per tensor per tile
#define NCOPY  32
#define NTOT   (16384LL * 2048LL)
#define KOFF   16384.0f
#define MAGIC  8388608.0f             // 2^23; RZ-FMA -> 2^23 + floor(g*9.9999)

__device__ double             g_ls[NCOPY][BINS];   // zero-init at module load
__device__ unsigned long long g_cs[NCOPY][BINS];
__device__ unsigned int       g_done;

__device__ __forceinline__ uint32_t smem_u32(const void* p) {
    return (uint32_t)__cvta_generic_to_shared(p);
}

__device__ __forceinline__ void mbar_wait(uint32_t mbar, uint32_t parity) {
    asm volatile(
        "{\n\t"
        ".reg .pred P;\n\t"
        "WL_%=:\n\t"
        "mbarrier.try_wait.parity.acquire.cta.shared::cta.b64 P, [%0], %1, 0x989680;\n\t"
        "@P bra WD_%=;\n\t"
        "bra WL_%=;\n\t"
        "WD_%=:\n\t"
        "}"
        :: "r"(mbar), "r"(parity) : "memory");
}

__device__ __forceinline__ void bulk_pair(uint32_t dx, const char* sx,
                                          uint32_t dt, const char* st,
                                          uint32_t mbar) {
    asm volatile("mbarrier.arrive.expect_tx.shared.b64 _, [%0], %1;"
                 :: "r"(mbar), "r"(2 * TILE_BYTES) : "memory");
    asm volatile("cp.async.bulk.shared::cta.global.mbarrier::complete_tx::bytes [%0], [%1], %2, [%3];"
                 :: "r"(dx), "l"(sx), "r"(TILE_BYTES), "r"(mbar) : "memory");
    asm volatile("cp.async.bulk.shared::cta.global.mbarrier::complete_tx::bytes [%0], [%1], %2, [%3];"
                 :: "r"(dt), "l"(st), "r"(TILE_BYTES), "r"(mbar) : "memory");
}

__device__ __forceinline__ void proc(float xx, float tt, float* __restrict__ h)
{
    float g   = fabsf(xx - tt);
    // RZ-FMA truncates toward zero; ulp=1 at 2^23 -> low bits = floor(g*9.9999)
    int   bin = __float_as_int(__fmaf_rz(g, 9.9999f, MAGIC)) & 15;
    float a   = __log2f(xx);
    float b2  = __log2f(1.0f - xx);
    float add = fmaf(tt, b2 - a, KOFF - b2);   // K - (-loss/ln2)
    h[bin * TPB] += add;
}

__global__ void __launch_bounds__(TPB, 8) ghm_kernel(
    const float4* __restrict__ x4,
    const float4* __restrict__ t4,
    float* __restrict__ out)
{
    __shared__ float hist[BINS * TPB];                    // 10 KB
    __shared__ alignas(16) float4 sx[2][TPB];             // 8 KB
    __shared__ alignas(16) float4 st[2][TPB];             // 8 KB
    __shared__ alignas(8) unsigned long long mbar[2];
    __shared__ double s_ls[BINS], s_cs[BINS];
    __shared__ int s_last;

    const int tid = threadIdx.x;
    float* __restrict__ h = &hist[tid];

#pragma unroll
    for (int b = 0; b < BINS; b++) h[b * TPB] = 0.0f;

    if (tid == 0) {
        asm volatile("mbarrier.init.shared.b64 [%0], 1;" :: "r"(smem_u32(&mbar[0])) : "memory");
        asm volatile("mbarrier.init.shared.b64 [%0], 1;" :: "r"(smem_u32(&mbar[1])) : "memory");
        asm volatile("fence.proxy.async.shared::cta;" ::: "memory");
    }
    __syncthreads();

    const int ntiles = FULLT + (blockIdx.x < XBLK ? 1 : 0);
    const char* gx = (const char*)x4;
    const char* gt = (const char*)t4;

    // prologue: issue tile 0 into stage 0
    if (tid == 0) {
        long goff = (long)blockIdx.x * TILE_BYTES;
        bulk_pair(smem_u32(&sx[0][0]), gx + goff,
                  smem_u32(&st[0][0]), gt + goff, smem_u32(&mbar[0]));
    }

    int ph0 = 0, ph1 = 0;
    for (int t = 0; t < ntiles; t++) {
        const int s = t & 1;
        // issue tile t+1 into the other stage (its previous contents, tile
        // t-1, were released by the __syncthreads at the end of iter t-1)
        if (t + 1 < ntiles && tid == 0) {
            long goff = ((long)(t + 1) * BLOCKS + blockIdx.x) * TILE_BYTES;
            bulk_pair(smem_u32(&sx[s ^ 1][0]), gx + goff,
                      smem_u32(&st[s ^ 1][0]), gt + goff, smem_u32(&mbar[s ^ 1]));
        }
        // wait for tile t
        if (s == 0) { mbar_wait(smem_u32(&mbar[0]), ph0); ph0 ^= 1; }
        else        { mbar_wait(smem_u32(&mbar[1]), ph1); ph1 ^= 1; }

        float4 xv = sx[s][tid];
        float4 tv = st[s][tid];
        proc(xv.x, tv.x, h);
        proc(xv.y, tv.y, h);
        proc(xv.z, tv.z, h);
        proc(xv.w, tv.w, h);
        __syncthreads();   // all reads of stage s done -> stage reusable
    }
    __syncthreads();

    // block reduction: warp w handles bins w and w+8
    const int wid = tid >> 5;
    const int lid = tid & 31;
    const int cp  = blockIdx.x & (NCOPY - 1);
    for (int bin = wid; bin < BINS; bin += 8) {
        float ls = 0.0f;
        int   c  = 0;
#pragma unroll
        for (int k = 0; k < TPB / 32; k++) {
            float v  = hist[bin * TPB + k * 32 + lid];
            int   ci = __float2int_rn(v * (1.0f / KOFF));
            ls += v - (float)ci * KOFF;
            c  += ci;
        }
#pragma unroll
        for (int o = 16; o > 0; o >>= 1) {
            ls += __shfl_down_sync(0xffffffffu, ls, o);
            c  += __shfl_down_sync(0xffffffffu, c, o);
        }
        if (lid == 0) {
            atomicAdd(&g_ls[cp][bin], (double)ls);
            atomicAdd(&g_cs[cp][bin], (unsigned long long)c);
        }
    }

    // ---- last-block finalize ----
    if (tid == 0) {
        __threadfence();
        unsigned old = atomicAdd(&g_done, 1u);
        s_last = (old == (unsigned)(BLOCKS - 1)) ? 1 : 0;
    }
    __syncthreads();
    if (!s_last) return;

    if (tid < BINS) {
        double a = 0.0;
        unsigned long long c = 0ull;
#pragma unroll
        for (int k = 0; k < NCOPY; k++) {
            a += ((volatile double*)&g_ls[k][tid])[0];
            c += ((volatile unsigned long long*)&g_cs[k][tid])[0];
        }
        s_ls[tid] = a;
        s_cs[tid] = (double)c;
    }
    __syncthreads();

    if (tid == 0) {
        const double N = (double)NTOT;
        int ne = 0;
#pragma unroll
        for (int b = 0; b < BINS; b++) ne += (s_cs[b] > 0.0) ? 1 : 0;
        double tot = 0.0;
#pragma unroll
        for (int b = 0; b < BINS; b++) {
            double gd = s_cs[b] * (double)ne;
            if (gd < 1.0) gd = 1.0;
            tot += s_ls[b] * (N / gd);
        }
        out[0] = (float)(tot * 0.6931471805599453 / N);   // log2 -> ln
    }
    __syncthreads();   // reads of g_ls/g_cs complete before reset

    for (int i = tid; i < NCOPY * BINS; i += TPB) {
        g_ls[i / BINS][i % BINS] = 0.0;
        g_cs[i / BINS][i % BINS] = 0ull;
    }
    if (tid == 0) g_done = 0u;
}

extern "C" void kernel_launch(void* const* d_in, const int* in_sizes, int n_in,
                              void* d_out, int out_size)
{
    const float4* x4 = (const float4*)d_in[0];
    const float4* t4 = (const float4*)d_in[1];
    float* out = (float*)d_out;

    ghm_kernel<<<BLOCKS, TPB>>>(x4, t4, out);
}